// round 1
// baseline (speedup 1.0000x reference)
#include <cuda_runtime.h>

// Fused embedding: out[row] = num_weight[n-1]*val + num_bias[n-1]  if input_to_numeric[id]=n>0
//                           = cat_table[input_to_categorical[id]]  otherwise
// One warp per row (B*L rows), D=128 fp32 = 32 lanes x float4.

__global__ void __launch_bounds__(256) emb_fused_kernel(
    const int*    __restrict__ fid,      // [B*L]
    const float*  __restrict__ fval,     // [B*L]
    const float4* __restrict__ cat,      // [N_CAT, 32] as float4
    const float4* __restrict__ w,        // [N_NUM, 32]
    const float4* __restrict__ b,        // [N_NUM, 32]
    const int*    __restrict__ to_num,   // [VOCAB+1]
    const int*    __restrict__ to_cat,   // [VOCAB+1]
    float4*       __restrict__ out,      // [B*L, 32]
    int n_rows)
{
    const int warps_per_block = blockDim.x >> 5;
    int row  = blockIdx.x * warps_per_block + (threadIdx.x >> 5);
    int lane = threadIdx.x & 31;
    if (row >= n_rows) return;

    int id   = __ldg(&fid[row]);
    int nidx = __ldg(&to_num[id]);

    float4 r;
    if (nidx > 0) {
        float  v  = __ldg(&fval[row]);
        long   base = (long)(nidx - 1) * 32 + lane;
        float4 wv = __ldg(&w[base]);
        float4 bv = __ldg(&b[base]);
        r.x = fmaf(wv.x, v, bv.x);
        r.y = fmaf(wv.y, v, bv.y);
        r.z = fmaf(wv.z, v, bv.z);
        r.w = fmaf(wv.w, v, bv.w);
    } else {
        int c = __ldg(&to_cat[id]);
        r = __ldg(&cat[(long)c * 32 + lane]);
    }
    out[(long)row * 32 + lane] = r;
}

extern "C" void kernel_launch(void* const* d_in, const int* in_sizes, int n_in,
                              void* d_out, int out_size)
{
    const int*    fid    = (const int*)   d_in[0];  // feature_ids [B,L] int32
    const float*  fval   = (const float*) d_in[1];  // feature_values [B,L]
    const float4* cat    = (const float4*)d_in[2];  // cat_table [N_CAT,128]
    const float4* w      = (const float4*)d_in[3];  // num_weight [N_NUM,128]
    const float4* b      = (const float4*)d_in[4];  // num_bias [N_NUM,128]
    const int*    to_num = (const int*)   d_in[5];  // input_to_numeric [VOCAB+1]
    const int*    to_cat = (const int*)   d_in[6];  // input_to_categorical [VOCAB+1]
    float4*       out    = (float4*)      d_out;

    int n_rows = in_sizes[0];                 // B*L = 262144
    int warps_per_block = 8;                  // 256 threads
    int blocks = (n_rows + warps_per_block - 1) / warps_per_block;
    emb_fused_kernel<<<blocks, 256>>>(fid, fval, cat, w, b, to_num, to_cat, out, n_rows);
}

// round 2
// speedup vs baseline: 1.5073x; 1.5073x over previous
#include <cuda_runtime.h>

// Fused embedding, warp-cooperative:
//  - warp owns 32 consecutive rows; lane r loads the scalars for row base+r
//    (coalesced fid/to_num/to_cat/fval; dependent-chain executed once at MLP=32)
//  - loop over 32 rows: shfl-broadcast indices, gather float4 (lane = column/4),
//    warp-uniform branch num vs cat path, streaming store.

#define VOCAB_GUARD 1

__global__ void __launch_bounds__(256) emb_fused_kernel(
    const int*    __restrict__ fid,      // [B*L]
    const float*  __restrict__ fval,     // [B*L]
    const float4* __restrict__ cat,      // [N_CAT, 32] as float4
    const float4* __restrict__ w,        // [N_NUM, 32]
    const float4* __restrict__ b,        // [N_NUM, 32]
    const int*    __restrict__ to_num,   // [VOCAB+1]
    const int*    __restrict__ to_cat,   // [VOCAB+1]
    float4*       __restrict__ out,      // [B*L, 32]
    int n_rows)
{
    const int lane = threadIdx.x & 31;
    const int warp_global = blockIdx.x * (blockDim.x >> 5) + (threadIdx.x >> 5);
    const long base = (long)warp_global * 32;
    if (base >= n_rows) return;

    // Per-lane scalar stage: lane r handles row base+r (coalesced, MLP=32 across warp)
    long my_row = base + lane;
    int   id   = 0;
    float v    = 0.0f;
    if (my_row < n_rows) {
        id = __ldg(&fid[my_row]);
        v  = __ldg(&fval[my_row]);
    }
    int nidx = __ldg(&to_num[id]);
    int cidx = __ldg(&to_cat[id]);

    const int rows_here = (int)min((long)32, n_rows - base);

    #pragma unroll 8
    for (int r = 0; r < 32; r++) {
        if (r >= rows_here) break;
        int   nr = __shfl_sync(0xffffffffu, nidx, r);
        float4 res;
        if (nr > 0) {
            float vr = __shfl_sync(0xffffffffu, v, r);
            long  o  = (long)(nr - 1) * 32 + lane;
            float4 wv = __ldg(&w[o]);
            float4 bv = __ldg(&b[o]);
            res.x = fmaf(wv.x, vr, bv.x);
            res.y = fmaf(wv.y, vr, bv.y);
            res.z = fmaf(wv.z, vr, bv.z);
            res.w = fmaf(wv.w, vr, bv.w);
        } else {
            int cr = __shfl_sync(0xffffffffu, cidx, r);
            res = __ldg(&cat[(long)cr * 32 + lane]);
        }
        // Streaming store: output is write-once, 134 MB >> L2; don't pollute L2.
        __stcs(&out[(base + r) * 32 + lane], res);
    }
}

extern "C" void kernel_launch(void* const* d_in, const int* in_sizes, int n_in,
                              void* d_out, int out_size)
{
    const int*    fid    = (const int*)   d_in[0];  // feature_ids [B,L] int32
    const float*  fval   = (const float*) d_in[1];  // feature_values [B,L]
    const float4* cat    = (const float4*)d_in[2];  // cat_table [N_CAT,128]
    const float4* w      = (const float4*)d_in[3];  // num_weight [N_NUM,128]
    const float4* b      = (const float4*)d_in[4];  // num_bias [N_NUM,128]
    const int*    to_num = (const int*)   d_in[5];  // input_to_numeric [VOCAB+1]
    const int*    to_cat = (const int*)   d_in[6];  // input_to_categorical [VOCAB+1]
    float4*       out    = (float4*)      d_out;

    int n_rows = in_sizes[0];                         // B*L = 262144
    int rows_per_block = 8 * 32;                      // 8 warps x 32 rows
    int blocks = (n_rows + rows_per_block - 1) / rows_per_block;  // 1024
    emb_fused_kernel<<<blocks, 256>>>(fid, fval, cat, w, b, to_num, to_cat, out, n_rows);
}

// round 3
// speedup vs baseline: 1.5891x; 1.0543x over previous
#include <cuda_runtime.h>

// Fused embedding, warp-cooperative, round 3:
//  - 128-thread blocks (4 warps) -> 2048 blocks: finer wave granularity across 148 SMs
//  - single packed shfl per row: bit31 = isnum, low bits = gather row
//  - fully unrolled 32-row loop, no bounds checks (n_rows = 1024*256 exact; tail
//    handled by launching an extra guarded block only if needed)

__global__ void __launch_bounds__(128) emb_fused_kernel(
    const int*    __restrict__ fid,      // [B*L]
    const float*  __restrict__ fval,     // [B*L]
    const float4* __restrict__ cat,      // [N_CAT, 32] as float4
    const float4* __restrict__ w,        // [N_NUM, 32]
    const float4* __restrict__ b,        // [N_NUM, 32]
    const int*    __restrict__ to_num,   // [VOCAB+1]
    const int*    __restrict__ to_cat,   // [VOCAB+1]
    float4*       __restrict__ out)      // [B*L, 32]
{
    const int lane = threadIdx.x & 31;
    const int warp_global = blockIdx.x * (blockDim.x >> 5) + (threadIdx.x >> 5);
    const long base = (long)warp_global * 32;

    // Per-lane scalar stage for row base+lane (coalesced, chain runs once at MLP=32)
    const long my_row = base + lane;
    const int   id  = __ldg(&fid[my_row]);
    const float v   = __ldg(&fval[my_row]);
    const int  nidx = __ldg(&to_num[id]);
    const int  cidx = __ldg(&to_cat[id]);

    // packed: numeric -> (nidx-1) | signbit ; categorical -> cidx (>= 0)
    const int packed = (nidx > 0) ? ((nidx - 1) | 0x80000000) : cidx;

    #pragma unroll
    for (int r = 0; r < 32; r++) {
        const int p = __shfl_sync(0xffffffffu, packed, r);
        float4 res;
        if (p < 0) {
            const float vr = __shfl_sync(0xffffffffu, v, r);
            const long  o  = (long)(p & 0x7fffffff) * 32 + lane;
            const float4 wv = __ldg(&w[o]);
            const float4 bv = __ldg(&b[o]);
            res.x = fmaf(wv.x, vr, bv.x);
            res.y = fmaf(wv.y, vr, bv.y);
            res.z = fmaf(wv.z, vr, bv.z);
            res.w = fmaf(wv.w, vr, bv.w);
        } else {
            res = __ldg(&cat[(long)p * 32 + lane]);
        }
        __stcs(&out[(base + r) * 32 + lane], res);
    }
}

// Tail kernel for the (unused here, but safe) case n_rows % 32 != 0
__global__ void __launch_bounds__(128) emb_tail_kernel(
    const int*    __restrict__ fid,
    const float*  __restrict__ fval,
    const float4* __restrict__ cat,
    const float4* __restrict__ w,
    const float4* __restrict__ b,
    const int*    __restrict__ to_num,
    const int*    __restrict__ to_cat,
    float4*       __restrict__ out,
    int start_row, int n_rows)
{
    int row  = start_row + blockIdx.x * (blockDim.x >> 5) + (threadIdx.x >> 5);
    int lane = threadIdx.x & 31;
    if (row >= n_rows) return;
    int id   = __ldg(&fid[row]);
    int nidx = __ldg(&to_num[id]);
    float4 r;
    if (nidx > 0) {
        float v = __ldg(&fval[row]);
        long  o = (long)(nidx - 1) * 32 + lane;
        float4 wv = __ldg(&w[o]);
        float4 bv = __ldg(&b[o]);
        r.x = fmaf(wv.x, v, bv.x);
        r.y = fmaf(wv.y, v, bv.y);
        r.z = fmaf(wv.z, v, bv.z);
        r.w = fmaf(wv.w, v, bv.w);
    } else {
        int c = __ldg(&to_cat[id]);
        r = __ldg(&cat[(long)c * 32 + lane]);
    }
    __stcs(&out[(long)row * 32 + lane], r);
}

extern "C" void kernel_launch(void* const* d_in, const int* in_sizes, int n_in,
                              void* d_out, int out_size)
{
    const int*    fid    = (const int*)   d_in[0];
    const float*  fval   = (const float*) d_in[1];
    const float4* cat    = (const float4*)d_in[2];
    const float4* w      = (const float4*)d_in[3];
    const float4* b      = (const float4*)d_in[4];
    const int*    to_num = (const int*)   d_in[5];
    const int*    to_cat = (const int*)   d_in[6];
    float4*       out    = (float4*)      d_out;

    const int n_rows = in_sizes[0];                 // 262144
    const int rows_per_block = 4 * 32;              // 4 warps x 32 rows
    const int full_blocks = n_rows / rows_per_block;
    if (full_blocks > 0)
        emb_fused_kernel<<<full_blocks, 128>>>(fid, fval, cat, w, b, to_num, to_cat, out);
    const int done = full_blocks * rows_per_block;
    const int rem  = n_rows - done;
    if (rem > 0) {
        int tb = (rem + 3) / 4;
        emb_tail_kernel<<<tb, 128>>>(fid, fval, cat, w, b, to_num, to_cat, out, done, n_rows);
    }
}